// round 1
// baseline (speedup 1.0000x reference)
#include <cuda_runtime.h>
#include <cstddef>

#define NN 50000
#define NE 800000
#define NG 512
#define HD 96
#define DHD 192
#define BN_EPS 1e-5f

// ---------------- scratch (device globals; no allocation allowed) ----------------
__device__ float g_agg[NN * HD];
__device__ float g_z[NN * DHD];
__device__ float g_h[NN * HD];
__device__ float g_post[NN * HD];
__device__ float g_pooled[NG * HD];
__device__ float g_vin[NG * HD];
__device__ float g_t1[NG * DHD];
__device__ float g_t2[NG * HD];
__device__ float g_sum[DHD];
__device__ float g_sumsq[DHD];
__device__ float g_scale[DHD];
__device__ float g_shift[DHD];
__device__ float g_counts[NG];

// ---------------- small utility kernels ----------------
__global__ void zero_kernel(float* __restrict__ p, int n) {
    int i = blockIdx.x * blockDim.x + threadIdx.x;
    int stride = gridDim.x * blockDim.x;
    for (; i < n; i += stride) p[i] = 0.f;
}

__global__ void zero_stats_kernel() {
    int i = threadIdx.x;
    if (i < DHD) { g_sum[i] = 0.f; g_sumsq[i] = 0.f; }
}

__global__ void counts_kernel(const int* __restrict__ batch) {
    int i = blockIdx.x * blockDim.x + threadIdx.x;
    if (i < NN) atomicAdd(&g_counts[batch[i]], 1.0f);
}

// messages flow src -> dst: agg[dst] += h[src]
__global__ void agg_kernel(const float* __restrict__ h,
                           const int* __restrict__ src,
                           const int* __restrict__ dst) {
    int e = blockIdx.x * blockDim.y + threadIdx.y;
    if (e < NE) {
        int s = src[e];
        int d = dst[e];
        int f = threadIdx.x;
        atomicAdd(&g_agg[(size_t)d * HD + f], h[(size_t)s * HD + f]);
    }
}

// ---------------- tiled fp32 GEMM: C[M,NC] = op(A[M,K]) @ B[K,NC] + bias ----------------
// AMODE 0: A as-is; 1: A + A2 (elementwise); 2: relu(A*g_scale[k] + g_shift[k]) (BN+ReLU on load)
template <int AMODE>
__global__ void __launch_bounds__(256) gemm_kernel(
    const float* __restrict__ A, const float* __restrict__ A2,
    const float* __restrict__ B, const float* __restrict__ bias,
    float* __restrict__ C, int M, int K, int NC)
{
    __shared__ float As[32][128];
    __shared__ float Bs[32][32];
    int tid = threadIdx.x;
    int tx = tid & 7;    // 0..7  -> 4 cols each  (32 cols)
    int ty = tid >> 3;   // 0..31 -> 4 rows each  (128 rows)
    int r0 = blockIdx.x * 128;
    int n0 = blockIdx.y * 32;
    float acc[4][4];
#pragma unroll
    for (int i = 0; i < 4; i++)
#pragma unroll
        for (int j = 0; j < 4; j++) acc[i][j] = 0.f;

    for (int k0 = 0; k0 < K; k0 += 32) {
        // load A tile (128 x 32) as float4, transform on load, store transposed
#pragma unroll
        for (int i = 0; i < 4; i++) {
            int idx4 = tid + i * 256;       // 0..1023
            int row = idx4 >> 3;            // 0..127
            int kk  = (idx4 & 7) << 2;      // 0,4,...,28
            float4 v = make_float4(0.f, 0.f, 0.f, 0.f);
            int gr = r0 + row;
            if (gr < M) {
                v = *(const float4*)(A + (size_t)gr * K + k0 + kk);
                if (AMODE == 1) {
                    float4 w = *(const float4*)(A2 + (size_t)gr * K + k0 + kk);
                    v.x += w.x; v.y += w.y; v.z += w.z; v.w += w.w;
                } else if (AMODE == 2) {
                    int kc = k0 + kk;
                    v.x = fmaxf(fmaf(v.x, g_scale[kc + 0], g_shift[kc + 0]), 0.f);
                    v.y = fmaxf(fmaf(v.y, g_scale[kc + 1], g_shift[kc + 1]), 0.f);
                    v.z = fmaxf(fmaf(v.z, g_scale[kc + 2], g_shift[kc + 2]), 0.f);
                    v.w = fmaxf(fmaf(v.w, g_scale[kc + 3], g_shift[kc + 3]), 0.f);
                }
            }
            As[kk + 0][row] = v.x;
            As[kk + 1][row] = v.y;
            As[kk + 2][row] = v.z;
            As[kk + 3][row] = v.w;
        }
        // load B tile (32 x 32)
        {
            int row = tid >> 3;            // k 0..31
            int cc  = (tid & 7) << 2;      // 0..28
            *(float4*)&Bs[row][cc] =
                *(const float4*)(B + (size_t)(k0 + row) * NC + n0 + cc);
        }
        __syncthreads();
#pragma unroll
        for (int kk = 0; kk < 32; kk++) {
            float4 a = *(const float4*)&As[kk][ty << 2];
            float4 b = *(const float4*)&Bs[kk][tx << 2];
            float ar[4] = {a.x, a.y, a.z, a.w};
            float br[4] = {b.x, b.y, b.z, b.w};
#pragma unroll
            for (int i = 0; i < 4; i++)
#pragma unroll
                for (int j = 0; j < 4; j++)
                    acc[i][j] = fmaf(ar[i], br[j], acc[i][j]);
        }
        __syncthreads();
    }
    float bb[4];
#pragma unroll
    for (int j = 0; j < 4; j++) bb[j] = bias[n0 + (tx << 2) + j];
#pragma unroll
    for (int i = 0; i < 4; i++) {
        int gr = r0 + (ty << 2) + i;
        if (gr < M) {
            float* cp = C + (size_t)gr * NC + n0 + (tx << 2);
#pragma unroll
            for (int j = 0; j < 4; j++) cp[j] = acc[i][j] + bb[j];
        }
    }
}

// ---------------- column stats (training-mode BN): sum & sumsq per column ----------------
__global__ void colstats_kernel(const float* __restrict__ A, int M, int NC) {
    int c = threadIdx.x;               // blockDim.x == NC
    float s = 0.f, s2 = 0.f;
    for (int r = blockIdx.x; r < M; r += gridDim.x) {
        float v = A[(size_t)r * NC + c];
        s += v;
        s2 = fmaf(v, v, s2);
    }
    atomicAdd(&g_sum[c], s);
    atomicAdd(&g_sumsq[c], s2);
}

__global__ void finalize_kernel(const float* __restrict__ gamma,
                                const float* __restrict__ beta,
                                int NC, float invM) {
    int c = threadIdx.x;
    if (c < NC) {
        float mean = g_sum[c] * invM;
        float var = g_sumsq[c] * invM - mean * mean;
        float sc = gamma[c] * rsqrtf(var + BN_EPS);
        g_scale[c] = sc;
        g_shift[c] = fmaf(-mean, sc, beta[c]);
    }
}

// ---------------- fused elementwise stages ----------------
// post = relu(bn(h)) + vn_embed  (layer-1 epilogue + first virtual-node add)
__global__ void post1_kernel(const float* __restrict__ vn) {
    int node = blockIdx.x * blockDim.y + threadIdx.y;
    if (node >= NN) return;
    int f = threadIdx.x;
    size_t idx = (size_t)node * HD + f;
    g_post[idx] = fmaxf(fmaf(g_h[idx], g_scale[f], g_shift[f]), 0.f) + vn[f];
}

// post = relu(bn(h)); pooled[batch] += post
__global__ void post2_kernel(const int* __restrict__ batch) {
    int node = blockIdx.x * blockDim.y + threadIdx.y;
    if (node >= NN) return;
    int f = threadIdx.x;
    size_t idx = (size_t)node * HD + f;
    float p = fmaxf(fmaf(g_h[idx], g_scale[f], g_shift[f]), 0.f);
    g_post[idx] = p;
    atomicAdd(&g_pooled[batch[node] * HD + f], p);
}

// vin = pooled + vn_embed (broadcast row)
__global__ void vin_kernel(const float* __restrict__ vn) {
    int i = blockIdx.x * blockDim.x + threadIdx.x;
    if (i < NG * HD) g_vin[i] = g_pooled[i] + vn[i % HD];
}

// post += relu(bn2(t2))[batch]   (second vmlp BN+ReLU applied lazily)
__global__ void post3_kernel(const int* __restrict__ batch) {
    int node = blockIdx.x * blockDim.y + threadIdx.y;
    if (node >= NN) return;
    int f = threadIdx.x;
    size_t idx = (size_t)node * HD + f;
    float v = g_t2[batch[node] * HD + f];
    g_post[idx] += fmaxf(fmaf(v, g_scale[f], g_shift[f]), 0.f);
}

// out[batch] += bn(h)  (final layer: BN without ReLU, summed for mean-pool)
__global__ void readout_kernel(const int* __restrict__ batch, float* __restrict__ out) {
    int node = blockIdx.x * blockDim.y + threadIdx.y;
    if (node >= NN) return;
    int f = threadIdx.x;
    size_t idx = (size_t)node * HD + f;
    float v = fmaf(g_h[idx], g_scale[f], g_shift[f]);
    atomicAdd(&out[batch[node] * HD + f], v);
}

__global__ void div_kernel(float* __restrict__ out) {
    int i = blockIdx.x * blockDim.x + threadIdx.x;
    if (i < NG * HD) out[i] /= fmaxf(g_counts[i / HD], 1.0f);
}

// ---------------- launch ----------------
extern "C" void kernel_launch(void* const* d_in, const int* in_sizes, int n_in,
                              void* d_out, int out_size) {
    const float* x      = (const float*)d_in[0];
    const int*   edge   = (const int*)d_in[1];
    const int*   batch  = (const int*)d_in[2];
    // d_in[3] = num_graphs (scalar, compile-time NG)
    const float* vn     = (const float*)d_in[4];
    const float* c1_W1  = (const float*)d_in[5];
    const float* c1_b1  = (const float*)d_in[6];
    const float* c1_g1  = (const float*)d_in[7];
    const float* c1_be1 = (const float*)d_in[8];
    const float* c1_W2  = (const float*)d_in[9];
    const float* c1_b2  = (const float*)d_in[10];
    const float* bn1_g  = (const float*)d_in[11];
    const float* bn1_b  = (const float*)d_in[12];
    const float* cs_W1  = (const float*)d_in[13];
    const float* cs_b1  = (const float*)d_in[14];
    const float* cs_g1  = (const float*)d_in[15];
    const float* cs_be1 = (const float*)d_in[16];
    const float* cs_W2  = (const float*)d_in[17];
    const float* cs_b2  = (const float*)d_in[18];
    const float* bns_g  = (const float*)d_in[19];
    const float* bns_b  = (const float*)d_in[20];
    const float* vm_W1  = (const float*)d_in[21];
    const float* vm_b1  = (const float*)d_in[22];
    const float* vm_g1  = (const float*)d_in[23];
    const float* vm_be1 = (const float*)d_in[24];
    const float* vm_W2  = (const float*)d_in[25];
    const float* vm_b2  = (const float*)d_in[26];
    const float* vm_g2  = (const float*)d_in[27];
    const float* vm_be2 = (const float*)d_in[28];
    float* out = (float*)d_out;

    const int* src = edge;
    const int* dst = edge + NE;

    float *p_agg, *p_z, *p_h, *p_post, *p_pooled, *p_vin, *p_t1, *p_t2, *p_counts;
    cudaGetSymbolAddress((void**)&p_agg, g_agg);
    cudaGetSymbolAddress((void**)&p_z, g_z);
    cudaGetSymbolAddress((void**)&p_h, g_h);
    cudaGetSymbolAddress((void**)&p_post, g_post);
    cudaGetSymbolAddress((void**)&p_pooled, g_pooled);
    cudaGetSymbolAddress((void**)&p_vin, g_vin);
    cudaGetSymbolAddress((void**)&p_t1, g_t1);
    cudaGetSymbolAddress((void**)&p_t2, g_t2);
    cudaGetSymbolAddress((void**)&p_counts, g_counts);

    dim3 ew(96, 4);
    int ewg = (NN + 3) / 4;
    dim3 aggB(96, 4);
    int aggG = (NE + 3) / 4;
    const float invN = 1.0f / (float)NN;
    const float invG = 1.0f / (float)NG;

    auto ggrid = [](int M, int NC) { return dim3((M + 127) / 128, NC / 32); };

    // graph counts
    zero_kernel<<<1, 512>>>(p_counts, NG);
    counts_kernel<<<(NN + 255) / 256, 256>>>(batch);

    // ---- layer 1 (conv1 on x) ----
    zero_kernel<<<2048, 256>>>(p_agg, NN * HD);
    agg_kernel<<<aggG, aggB>>>(x, src, dst);
    gemm_kernel<1><<<ggrid(NN, DHD), 256>>>(x, p_agg, c1_W1, c1_b1, p_z, NN, HD, DHD);
    zero_stats_kernel<<<1, DHD>>>();
    colstats_kernel<<<512, DHD>>>(p_z, NN, DHD);
    finalize_kernel<<<1, DHD>>>(c1_g1, c1_be1, DHD, invN);
    gemm_kernel<2><<<ggrid(NN, HD), 256>>>(p_z, nullptr, c1_W2, c1_b2, p_h, NN, DHD, HD);
    zero_stats_kernel<<<1, DHD>>>();
    colstats_kernel<<<512, HD>>>(p_h, NN, HD);
    finalize_kernel<<<1, HD>>>(bn1_g, bn1_b, HD, invN);
    post1_kernel<<<ewg, ew>>>(vn);

    // ---- layer 2 (cs[0]) ----
    zero_kernel<<<2048, 256>>>(p_agg, NN * HD);
    agg_kernel<<<aggG, aggB>>>(p_post, src, dst);
    gemm_kernel<1><<<ggrid(NN, DHD), 256>>>(p_post, p_agg, cs_W1, cs_b1, p_z, NN, HD, DHD);
    zero_stats_kernel<<<1, DHD>>>();
    colstats_kernel<<<512, DHD>>>(p_z, NN, DHD);
    finalize_kernel<<<1, DHD>>>(cs_g1, cs_be1, DHD, invN);
    gemm_kernel<2><<<ggrid(NN, HD), 256>>>(p_z, nullptr, cs_W2, cs_b2, p_h, NN, DHD, HD);
    zero_stats_kernel<<<1, DHD>>>();
    colstats_kernel<<<512, HD>>>(p_h, NN, HD);
    finalize_kernel<<<1, HD>>>(bns_g, bns_b, HD, invN);
    zero_kernel<<<64, 256>>>(p_pooled, NG * HD);
    post2_kernel<<<ewg, ew>>>(batch);

    // ---- virtual node MLP ----
    vin_kernel<<<(NG * HD + 255) / 256, 256>>>(vn);
    gemm_kernel<0><<<ggrid(NG, DHD), 256>>>(p_vin, nullptr, vm_W1, vm_b1, p_t1, NG, HD, DHD);
    zero_stats_kernel<<<1, DHD>>>();
    colstats_kernel<<<64, DHD>>>(p_t1, NG, DHD);
    finalize_kernel<<<1, DHD>>>(vm_g1, vm_be1, DHD, invG);
    gemm_kernel<2><<<ggrid(NG, HD), 256>>>(p_t1, nullptr, vm_W2, vm_b2, p_t2, NG, DHD, HD);
    zero_stats_kernel<<<1, DHD>>>();
    colstats_kernel<<<64, HD>>>(p_t2, NG, HD);
    finalize_kernel<<<1, HD>>>(vm_g2, vm_be2, HD, invG);
    post3_kernel<<<ewg, ew>>>(batch);

    // ---- layer 3 (cs[1]) ----
    zero_kernel<<<2048, 256>>>(p_agg, NN * HD);
    agg_kernel<<<aggG, aggB>>>(p_post, src, dst);
    gemm_kernel<1><<<ggrid(NN, DHD), 256>>>(p_post, p_agg, cs_W1 + HD * DHD, cs_b1 + DHD,
                                            p_z, NN, HD, DHD);
    zero_stats_kernel<<<1, DHD>>>();
    colstats_kernel<<<512, DHD>>>(p_z, NN, DHD);
    finalize_kernel<<<1, DHD>>>(cs_g1 + DHD, cs_be1 + DHD, DHD, invN);
    gemm_kernel<2><<<ggrid(NN, HD), 256>>>(p_z, nullptr, cs_W2 + DHD * HD, cs_b2 + HD,
                                           p_h, NN, DHD, HD);
    zero_stats_kernel<<<1, DHD>>>();
    colstats_kernel<<<512, HD>>>(p_h, NN, HD);
    finalize_kernel<<<1, HD>>>(bns_g + HD, bns_b + HD, HD, invN);

    // ---- mean-pool readout ----
    zero_kernel<<<64, 256>>>(out, NG * HD);
    readout_kernel<<<ewg, ew>>>(batch, out);
    div_kernel<<<(NG * HD + 255) / 256, 256>>>(out);
}

// round 2
// speedup vs baseline: 1.9340x; 1.9340x over previous
#include <cuda_runtime.h>
#include <cstddef>

#define NN 50000
#define NE 800000
#define NG 512
#define HD 96
#define DHD 192
#define BN_EPS 1e-5f
#define SCAN_BLOCKS 49   // ceil(50000/1024)

// ---------------- scratch (device globals; no allocation allowed) ----------------
__device__ float g_agg[NN * HD];
__device__ float g_z[NN * DHD];
__device__ float g_h[NN * HD];
__device__ float g_post[NN * HD];
__device__ float g_pooled[NG * HD];
__device__ float g_vin[NG * HD];
__device__ float g_t1[NG * DHD];
__device__ float g_t2[NG * HD];
__device__ float g_sum[DHD];
__device__ float g_sumsq[DHD];
__device__ float g_scale[DHD];
__device__ float g_shift[DHD];
__device__ float g_counts[NG];
// CSR scratch
__device__ int g_deg[NN];
__device__ int g_rowptr[NN + 1];
__device__ int g_cursor[NN];      // also used as temp for inclusive scan
__device__ int g_srclist[NE];
__device__ int g_boff[64];

// ---------------- small utility kernels ----------------
__global__ void zero_kernel(float* __restrict__ p, int n) {
    int i = blockIdx.x * blockDim.x + threadIdx.x;
    int stride = gridDim.x * blockDim.x;
    for (; i < n; i += stride) p[i] = 0.f;
}

__global__ void zero_int_kernel(int* __restrict__ p, int n) {
    int i = blockIdx.x * blockDim.x + threadIdx.x;
    if (i < n) p[i] = 0;
}

__global__ void zero_stats_kernel() {
    int i = threadIdx.x;
    if (i < DHD) { g_sum[i] = 0.f; g_sumsq[i] = 0.f; }
}

__global__ void counts_kernel(const int* __restrict__ batch) {
    int i = blockIdx.x * blockDim.x + threadIdx.x;
    if (i < NN) atomicAdd(&g_counts[batch[i]], 1.0f);
}

// ---------------- CSR build ----------------
__global__ void hist_kernel(const int* __restrict__ dst) {
    int i = blockIdx.x * blockDim.x + threadIdx.x;
    if (i < NE) atomicAdd(&g_deg[dst[i]], 1);
}

// inclusive scan within 1024-blocks; block totals to g_boff
__global__ void scan1_kernel() {
    __shared__ int sh[1024];
    int i = blockIdx.x * 1024 + threadIdx.x;
    int v = (i < NN) ? g_deg[i] : 0;
    sh[threadIdx.x] = v;
    __syncthreads();
#pragma unroll
    for (int off = 1; off < 1024; off <<= 1) {
        int t = (threadIdx.x >= off) ? sh[threadIdx.x - off] : 0;
        __syncthreads();
        sh[threadIdx.x] += t;
        __syncthreads();
    }
    if (i < NN) g_cursor[i] = sh[threadIdx.x];   // inclusive scan (temp)
    if (threadIdx.x == 1023) g_boff[blockIdx.x] = sh[1023];
}

// exclusive scan of block totals (tiny)
__global__ void scan2_kernel() {
    if (threadIdx.x == 0) {
        int run = 0;
        for (int b = 0; b < SCAN_BLOCKS; b++) {
            int t = g_boff[b];
            g_boff[b] = run;
            run += t;
        }
        g_rowptr[NN] = run;   // == NE
    }
}

// rowptr[i] = exclusive prefix; cursor[i] = same (scatter cursors)
__global__ void scan3_kernel() {
    int i = blockIdx.x * 1024 + threadIdx.x;
    if (i < NN) {
        int excl = g_cursor[i] - g_deg[i] + g_boff[blockIdx.x];
        g_rowptr[i] = excl;
        g_cursor[i] = excl;
    }
}

__global__ void scatter_kernel(const int* __restrict__ src, const int* __restrict__ dst) {
    int i = blockIdx.x * blockDim.x + threadIdx.x;
    if (i < NE) {
        int d = dst[i];
        int p = atomicAdd(&g_cursor[d], 1);
        g_srclist[p] = src[i];
    }
}

// ---------------- CSR aggregation: agg[i] = h[i] + sum_{j in N(i)} h[j] ----------------
__global__ void __launch_bounds__(384) agg_csr_kernel(const float* __restrict__ h) {
    int node = blockIdx.x * 4 + threadIdx.y;
    if (node >= NN) return;
    int f = threadIdx.x;
    int beg = g_rowptr[node];
    int end = g_rowptr[node + 1];
    float acc = h[(size_t)node * HD + f];
    int e = beg;
    for (; e + 4 <= end; e += 4) {
        int s0 = g_srclist[e + 0];
        int s1 = g_srclist[e + 1];
        int s2 = g_srclist[e + 2];
        int s3 = g_srclist[e + 3];
        float a0 = h[(size_t)s0 * HD + f];
        float a1 = h[(size_t)s1 * HD + f];
        float a2 = h[(size_t)s2 * HD + f];
        float a3 = h[(size_t)s3 * HD + f];
        acc += (a0 + a1) + (a2 + a3);
    }
    for (; e < end; e++) acc += h[(size_t)g_srclist[e] * HD + f];
    g_agg[(size_t)node * HD + f] = acc;
}

// ---------------- tiled fp32 GEMM: C[M,NC] = op(A[M,K]) @ B[K,NC] + bias ----------------
// AMODE 0: A as-is; 2: relu(A*g_scale[k] + g_shift[k]) (BN+ReLU on load)
// STATS 1: accumulate per-column sum/sumsq of C into g_sum/g_sumsq
template <int AMODE, int STATS>
__global__ void __launch_bounds__(256) gemm_kernel(
    const float* __restrict__ A,
    const float* __restrict__ B, const float* __restrict__ bias,
    float* __restrict__ C, int M, int K, int NC)
{
    __shared__ float As[32][128];
    __shared__ float Bs[32][32];
    __shared__ float ssum[8][32];
    __shared__ float ssq[8][32];
    int tid = threadIdx.x;
    int tx = tid & 7;    // 0..7  -> 4 cols each  (32 cols)
    int ty = tid >> 3;   // 0..31 -> 4 rows each  (128 rows)
    int r0 = blockIdx.x * 128;
    int n0 = blockIdx.y * 32;
    float acc[4][4];
#pragma unroll
    for (int i = 0; i < 4; i++)
#pragma unroll
        for (int j = 0; j < 4; j++) acc[i][j] = 0.f;

    for (int k0 = 0; k0 < K; k0 += 32) {
#pragma unroll
        for (int i = 0; i < 4; i++) {
            int idx4 = tid + i * 256;       // 0..1023
            int row = idx4 >> 3;            // 0..127
            int kk  = (idx4 & 7) << 2;      // 0,4,...,28
            float4 v = make_float4(0.f, 0.f, 0.f, 0.f);
            int gr = r0 + row;
            if (gr < M) {
                v = *(const float4*)(A + (size_t)gr * K + k0 + kk);
                if (AMODE == 2) {
                    int kc = k0 + kk;
                    v.x = fmaxf(fmaf(v.x, g_scale[kc + 0], g_shift[kc + 0]), 0.f);
                    v.y = fmaxf(fmaf(v.y, g_scale[kc + 1], g_shift[kc + 1]), 0.f);
                    v.z = fmaxf(fmaf(v.z, g_scale[kc + 2], g_shift[kc + 2]), 0.f);
                    v.w = fmaxf(fmaf(v.w, g_scale[kc + 3], g_shift[kc + 3]), 0.f);
                }
            }
            As[kk + 0][row] = v.x;
            As[kk + 1][row] = v.y;
            As[kk + 2][row] = v.z;
            As[kk + 3][row] = v.w;
        }
        {
            int row = tid >> 3;
            int cc  = (tid & 7) << 2;
            *(float4*)&Bs[row][cc] =
                *(const float4*)(B + (size_t)(k0 + row) * NC + n0 + cc);
        }
        __syncthreads();
#pragma unroll
        for (int kk = 0; kk < 32; kk++) {
            float4 a = *(const float4*)&As[kk][ty << 2];
            float4 b = *(const float4*)&Bs[kk][tx << 2];
            float ar[4] = {a.x, a.y, a.z, a.w};
            float br[4] = {b.x, b.y, b.z, b.w};
#pragma unroll
            for (int i = 0; i < 4; i++)
#pragma unroll
                for (int j = 0; j < 4; j++)
                    acc[i][j] = fmaf(ar[i], br[j], acc[i][j]);
        }
        __syncthreads();
    }
    float bb[4];
#pragma unroll
    for (int j = 0; j < 4; j++) bb[j] = bias[n0 + (tx << 2) + j];

    float s[4] = {0.f, 0.f, 0.f, 0.f};
    float q[4] = {0.f, 0.f, 0.f, 0.f};
#pragma unroll
    for (int i = 0; i < 4; i++) {
        int gr = r0 + (ty << 2) + i;
        if (gr < M) {
            float* cp = C + (size_t)gr * NC + n0 + (tx << 2);
#pragma unroll
            for (int j = 0; j < 4; j++) {
                float c = acc[i][j] + bb[j];
                cp[j] = c;
                if (STATS) { s[j] += c; q[j] = fmaf(c, c, q[j]); }
            }
        }
    }
    if (STATS) {
        // reduce over the 4 ty values within each warp (lanes differing in bits 3,4)
#pragma unroll
        for (int off = 8; off < 32; off <<= 1) {
#pragma unroll
            for (int j = 0; j < 4; j++) {
                s[j] += __shfl_xor_sync(0xFFFFFFFFu, s[j], off);
                q[j] += __shfl_xor_sync(0xFFFFFFFFu, q[j], off);
            }
        }
        int w = tid >> 5;
        int lane = tid & 31;
        if (lane < 8) {
#pragma unroll
            for (int j = 0; j < 4; j++) {
                ssum[w][lane * 4 + j] = s[j];
                ssq[w][lane * 4 + j] = q[j];
            }
        }
        __syncthreads();
        if (tid < 32) {
            float a = 0.f, b2 = 0.f;
#pragma unroll
            for (int w2 = 0; w2 < 8; w2++) { a += ssum[w2][tid]; b2 += ssq[w2][tid]; }
            atomicAdd(&g_sum[n0 + tid], a);
            atomicAdd(&g_sumsq[n0 + tid], b2);
        }
    }
}

// ---------------- BN finalize (also resets stat accumulators) ----------------
__global__ void finalize_kernel(const float* __restrict__ gamma,
                                const float* __restrict__ beta,
                                int NC, float invM) {
    int c = threadIdx.x;
    if (c < NC) {
        float mean = g_sum[c] * invM;
        float var = g_sumsq[c] * invM - mean * mean;
        float sc = gamma[c] * rsqrtf(var + BN_EPS);
        g_scale[c] = sc;
        g_shift[c] = fmaf(-mean, sc, beta[c]);
    }
    if (c < DHD) { g_sum[c] = 0.f; g_sumsq[c] = 0.f; }
}

// ---------------- fused elementwise stages ----------------
__global__ void post1_kernel(const float* __restrict__ vn) {
    int node = blockIdx.x * blockDim.y + threadIdx.y;
    if (node >= NN) return;
    int f = threadIdx.x;
    size_t idx = (size_t)node * HD + f;
    g_post[idx] = fmaxf(fmaf(g_h[idx], g_scale[f], g_shift[f]), 0.f) + vn[f];
}

__global__ void post2_kernel(const int* __restrict__ batch) {
    int node = blockIdx.x * blockDim.y + threadIdx.y;
    if (node >= NN) return;
    int f = threadIdx.x;
    size_t idx = (size_t)node * HD + f;
    float p = fmaxf(fmaf(g_h[idx], g_scale[f], g_shift[f]), 0.f);
    g_post[idx] = p;
    atomicAdd(&g_pooled[batch[node] * HD + f], p);
}

__global__ void vin_kernel(const float* __restrict__ vn) {
    int i = blockIdx.x * blockDim.x + threadIdx.x;
    if (i < NG * HD) g_vin[i] = g_pooled[i] + vn[i % HD];
}

__global__ void post3_kernel(const int* __restrict__ batch) {
    int node = blockIdx.x * blockDim.y + threadIdx.y;
    if (node >= NN) return;
    int f = threadIdx.x;
    size_t idx = (size_t)node * HD + f;
    float v = g_t2[batch[node] * HD + f];
    g_post[idx] += fmaxf(fmaf(v, g_scale[f], g_shift[f]), 0.f);
}

__global__ void readout_kernel(const int* __restrict__ batch, float* __restrict__ out) {
    int node = blockIdx.x * blockDim.y + threadIdx.y;
    if (node >= NN) return;
    int f = threadIdx.x;
    size_t idx = (size_t)node * HD + f;
    float v = fmaf(g_h[idx], g_scale[f], g_shift[f]);
    atomicAdd(&out[batch[node] * HD + f], v);
}

__global__ void div_kernel(float* __restrict__ out) {
    int i = blockIdx.x * blockDim.x + threadIdx.x;
    if (i < NG * HD) out[i] /= fmaxf(g_counts[i / HD], 1.0f);
}

// ---------------- launch ----------------
extern "C" void kernel_launch(void* const* d_in, const int* in_sizes, int n_in,
                              void* d_out, int out_size) {
    const float* x      = (const float*)d_in[0];
    const int*   edge   = (const int*)d_in[1];
    const int*   batch  = (const int*)d_in[2];
    const float* vn     = (const float*)d_in[4];
    const float* c1_W1  = (const float*)d_in[5];
    const float* c1_b1  = (const float*)d_in[6];
    const float* c1_g1  = (const float*)d_in[7];
    const float* c1_be1 = (const float*)d_in[8];
    const float* c1_W2  = (const float*)d_in[9];
    const float* c1_b2  = (const float*)d_in[10];
    const float* bn1_g  = (const float*)d_in[11];
    const float* bn1_b  = (const float*)d_in[12];
    const float* cs_W1  = (const float*)d_in[13];
    const float* cs_b1  = (const float*)d_in[14];
    const float* cs_g1  = (const float*)d_in[15];
    const float* cs_be1 = (const float*)d_in[16];
    const float* cs_W2  = (const float*)d_in[17];
    const float* cs_b2  = (const float*)d_in[18];
    const float* bns_g  = (const float*)d_in[19];
    const float* bns_b  = (const float*)d_in[20];
    const float* vm_W1  = (const float*)d_in[21];
    const float* vm_b1  = (const float*)d_in[22];
    const float* vm_g1  = (const float*)d_in[23];
    const float* vm_be1 = (const float*)d_in[24];
    const float* vm_W2  = (const float*)d_in[25];
    const float* vm_b2  = (const float*)d_in[26];
    const float* vm_g2  = (const float*)d_in[27];
    const float* vm_be2 = (const float*)d_in[28];
    float* out = (float*)d_out;

    const int* src = edge;
    const int* dst = edge + NE;

    float *p_agg, *p_z, *p_h, *p_post, *p_pooled, *p_vin, *p_t1, *p_t2, *p_counts;
    int *p_deg;
    cudaGetSymbolAddress((void**)&p_agg, g_agg);
    cudaGetSymbolAddress((void**)&p_z, g_z);
    cudaGetSymbolAddress((void**)&p_h, g_h);
    cudaGetSymbolAddress((void**)&p_post, g_post);
    cudaGetSymbolAddress((void**)&p_pooled, g_pooled);
    cudaGetSymbolAddress((void**)&p_vin, g_vin);
    cudaGetSymbolAddress((void**)&p_t1, g_t1);
    cudaGetSymbolAddress((void**)&p_t2, g_t2);
    cudaGetSymbolAddress((void**)&p_counts, g_counts);
    cudaGetSymbolAddress((void**)&p_deg, g_deg);

    dim3 ew(96, 4);
    int ewg = (NN + 3) / 4;
    const float invN = 1.0f / (float)NN;
    const float invG = 1.0f / (float)NG;
    auto ggrid = [](int M, int NC) { return dim3((M + 127) / 128, NC / 32); };
    int aggGrid = (NN + 3) / 4;

    // ---- one-time per launch: graph counts, CSR build, stat init ----
    zero_kernel<<<1, 512>>>(p_counts, NG);
    counts_kernel<<<(NN + 255) / 256, 256>>>(batch);
    zero_stats_kernel<<<1, DHD>>>();

    zero_int_kernel<<<(NN + 1023) / 1024, 1024>>>(p_deg, NN);
    hist_kernel<<<(NE + 255) / 256, 256>>>(dst);
    scan1_kernel<<<SCAN_BLOCKS, 1024>>>();
    scan2_kernel<<<1, 32>>>();
    scan3_kernel<<<SCAN_BLOCKS, 1024>>>();
    scatter_kernel<<<(NE + 255) / 256, 256>>>(src, dst);

    // ---- layer 1 (conv1 on x) ----
    agg_csr_kernel<<<aggGrid, ew>>>(x);
    gemm_kernel<0, 1><<<ggrid(NN, DHD), 256>>>(p_agg, c1_W1, c1_b1, p_z, NN, HD, DHD);
    finalize_kernel<<<1, DHD>>>(c1_g1, c1_be1, DHD, invN);
    gemm_kernel<2, 1><<<ggrid(NN, HD), 256>>>(p_z, c1_W2, c1_b2, p_h, NN, DHD, HD);
    finalize_kernel<<<1, DHD>>>(bn1_g, bn1_b, HD, invN);
    post1_kernel<<<ewg, ew>>>(vn);

    // ---- layer 2 (cs[0]) ----
    agg_csr_kernel<<<aggGrid, ew>>>(p_post);
    gemm_kernel<0, 1><<<ggrid(NN, DHD), 256>>>(p_agg, cs_W1, cs_b1, p_z, NN, HD, DHD);
    finalize_kernel<<<1, DHD>>>(cs_g1, cs_be1, DHD, invN);
    gemm_kernel<2, 1><<<ggrid(NN, HD), 256>>>(p_z, cs_W2, cs_b2, p_h, NN, DHD, HD);
    finalize_kernel<<<1, DHD>>>(bns_g, bns_b, HD, invN);
    zero_kernel<<<64, 256>>>(p_pooled, NG * HD);
    post2_kernel<<<ewg, ew>>>(batch);

    // ---- virtual node MLP ----
    vin_kernel<<<(NG * HD + 255) / 256, 256>>>(vn);
    gemm_kernel<0, 1><<<ggrid(NG, DHD), 256>>>(p_vin, vm_W1, vm_b1, p_t1, NG, HD, DHD);
    finalize_kernel<<<1, DHD>>>(vm_g1, vm_be1, DHD, invG);
    gemm_kernel<2, 1><<<ggrid(NG, HD), 256>>>(p_t1, vm_W2, vm_b2, p_t2, NG, DHD, HD);
    finalize_kernel<<<1, DHD>>>(vm_g2, vm_be2, HD, invG);
    post3_kernel<<<ewg, ew>>>(batch);

    // ---- layer 3 (cs[1]) ----
    agg_csr_kernel<<<aggGrid, ew>>>(p_post);
    gemm_kernel<0, 1><<<ggrid(NN, DHD), 256>>>(p_agg, cs_W1 + HD * DHD, cs_b1 + DHD,
                                               p_z, NN, HD, DHD);
    finalize_kernel<<<1, DHD>>>(cs_g1 + DHD, cs_be1 + DHD, DHD, invN);
    gemm_kernel<2, 1><<<ggrid(NN, HD), 256>>>(p_z, cs_W2 + DHD * HD, cs_b2 + HD,
                                              p_h, NN, DHD, HD);
    finalize_kernel<<<1, DHD>>>(bns_g + HD, bns_b + HD, HD, invN);

    // ---- mean-pool readout ----
    zero_kernel<<<64, 256>>>(out, NG * HD);
    readout_kernel<<<ewg, ew>>>(batch, out);
    div_kernel<<<(NG * HD + 255) / 256, 256>>>(out);
}

// round 3
// speedup vs baseline: 2.1981x; 1.1366x over previous
#include <cuda_runtime.h>
#include <cstddef>
#include <cstdint>

#define NN 50000
#define NE 800000
#define NG 512
#define HD 96
#define DHD 192
#define BN_EPS 1e-5f
#define SCAN_BLOCKS 49   // ceil(50000/1024)

// ---------------- scratch (device globals; no allocation allowed) ----------------
__device__ float g_agg[NN * HD];
__device__ float g_z[NN * DHD];
__device__ float g_h[NN * HD];
__device__ float g_post[NN * HD];
__device__ float g_pooled[NG * HD];
__device__ float g_vin[NG * HD];
__device__ float g_t1[NG * DHD];
__device__ float g_t2[NG * HD];
__device__ float g_sum[DHD];
__device__ float g_sumsq[DHD];
__device__ float g_scale[DHD];
__device__ float g_shift[DHD];
__device__ float g_counts[NG];
// CSR scratch
__device__ int g_deg[NN];
__device__ int g_rowptr[NN + 1];
__device__ int g_cursor[NN];
__device__ int g_srclist[NE];
__device__ int g_boff[64];

// ---------------- packed f32x2 helpers (sm_103a FFMA2 path) ----------------
__device__ __forceinline__ double ffma2(double a, double b, double c) {
    double r;
    asm("fma.rn.f32x2 %0, %1, %2, %3;" : "=d"(r) : "d"(a), "d"(b), "d"(c));
    return r;
}
__device__ __forceinline__ double dup2(float x) {
    double r;
    asm("mov.b64 %0, {%1, %1};" : "=d"(r) : "f"(x));
    return r;
}
__device__ __forceinline__ float2 unpack2(double v) {
    float2 r;
    asm("mov.b64 {%0, %1}, %2;" : "=f"(r.x), "=f"(r.y) : "d"(v));
    return r;
}
__device__ __forceinline__ double zero2() {
    double r;
    asm("mov.b64 %0, {%1, %1};" : "=d"(r) : "f"(0.0f));
    return r;
}

// ---------------- small utility kernels ----------------
__global__ void zero_kernel(float* __restrict__ p, int n) {
    int i = blockIdx.x * blockDim.x + threadIdx.x;
    int stride = gridDim.x * blockDim.x;
    for (; i < n; i += stride) p[i] = 0.f;
}

__global__ void zero_int_kernel(int* __restrict__ p, int n) {
    int i = blockIdx.x * blockDim.x + threadIdx.x;
    if (i < n) p[i] = 0;
}

__global__ void zero_stats_kernel() {
    int i = threadIdx.x;
    if (i < DHD) { g_sum[i] = 0.f; g_sumsq[i] = 0.f; }
}

__global__ void counts_kernel(const int* __restrict__ batch) {
    int i = blockIdx.x * blockDim.x + threadIdx.x;
    if (i < NN) atomicAdd(&g_counts[batch[i]], 1.0f);
}

// ---------------- CSR build ----------------
__global__ void hist_kernel(const int* __restrict__ dst) {
    int i = blockIdx.x * blockDim.x + threadIdx.x;
    if (i < NE) atomicAdd(&g_deg[dst[i]], 1);
}

__global__ void scan1_kernel() {
    __shared__ int sh[1024];
    int i = blockIdx.x * 1024 + threadIdx.x;
    int v = (i < NN) ? g_deg[i] : 0;
    sh[threadIdx.x] = v;
    __syncthreads();
#pragma unroll
    for (int off = 1; off < 1024; off <<= 1) {
        int t = (threadIdx.x >= off) ? sh[threadIdx.x - off] : 0;
        __syncthreads();
        sh[threadIdx.x] += t;
        __syncthreads();
    }
    if (i < NN) g_cursor[i] = sh[threadIdx.x];
    if (threadIdx.x == 1023) g_boff[blockIdx.x] = sh[1023];
}

__global__ void scan2_kernel() {
    if (threadIdx.x == 0) {
        int run = 0;
        for (int b = 0; b < SCAN_BLOCKS; b++) {
            int t = g_boff[b];
            g_boff[b] = run;
            run += t;
        }
        g_rowptr[NN] = run;
    }
}

__global__ void scan3_kernel() {
    int i = blockIdx.x * 1024 + threadIdx.x;
    if (i < NN) {
        int excl = g_cursor[i] - g_deg[i] + g_boff[blockIdx.x];
        g_rowptr[i] = excl;
        g_cursor[i] = excl;
    }
}

__global__ void scatter_kernel(const int* __restrict__ src, const int* __restrict__ dst) {
    int i = blockIdx.x * blockDim.x + threadIdx.x;
    if (i < NE) {
        int d = dst[i];
        int p = atomicAdd(&g_cursor[d], 1);
        g_srclist[p] = src[i];
    }
}

// ---------------- CSR aggregation: agg[i] = h[i] + sum_{j in N(i)} h[j] ----------------
__global__ void __launch_bounds__(384) agg_csr_kernel(const float* __restrict__ h) {
    int node = blockIdx.x * 4 + threadIdx.y;
    if (node >= NN) return;
    int f = threadIdx.x;
    int beg = g_rowptr[node];
    int end = g_rowptr[node + 1];
    float acc = h[(size_t)node * HD + f];
    int e = beg;
    for (; e + 4 <= end; e += 4) {
        int s0 = g_srclist[e + 0];
        int s1 = g_srclist[e + 1];
        int s2 = g_srclist[e + 2];
        int s3 = g_srclist[e + 3];
        float a0 = h[(size_t)s0 * HD + f];
        float a1 = h[(size_t)s1 * HD + f];
        float a2 = h[(size_t)s2 * HD + f];
        float a3 = h[(size_t)s3 * HD + f];
        acc += (a0 + a1) + (a2 + a3);
    }
    for (; e < end; e++) acc += h[(size_t)g_srclist[e] * HD + f];
    g_agg[(size_t)node * HD + f] = acc;
}

// ---------------- FFMA2 tiled fp32 GEMM: C[M,NC] = op(A[M,K]) @ B[K,NC] + bias ----------
// Block tile 128 x (TN*16), 256 threads, thread tile 8 x TN, f32x2 packed accumulators.
// AMODE 0: A as-is; 2: relu(A*g_scale[k]+g_shift[k]) (BN+ReLU on load)
// STATS 1: accumulate per-column sum/sumsq of C into g_sum/g_sumsq
template <int AMODE, int STATS, int TN>
__global__ void __launch_bounds__(256) gemm2_kernel(
    const float* __restrict__ A,
    const float* __restrict__ B, const float* __restrict__ bias,
    float* __restrict__ C, int M, int K, int NC)
{
    constexpr int BN = TN * 16;
    __shared__ float As[32][128];
    __shared__ float Bs[32][BN];
    __shared__ float ssum[8][BN];
    __shared__ float ssq[8][BN];

    int tid = threadIdx.x;
    int tx = tid & 15;    // 0..15 -> TN cols each
    int ty = tid >> 4;    // 0..15 -> 8 rows each
    int r0 = blockIdx.x * 128;
    int n0 = blockIdx.y * BN;

    double acc2[4][TN];
#pragma unroll
    for (int ip = 0; ip < 4; ip++)
#pragma unroll
        for (int j = 0; j < TN; j++) acc2[ip][j] = zero2();

    for (int k0 = 0; k0 < K; k0 += 32) {
        // A tile (128 rows x 32 k) -> transposed into As[kk][row]
#pragma unroll
        for (int i = 0; i < 4; i++) {
            int idx4 = tid + i * 256;      // 0..1023
            int row = idx4 >> 3;           // 0..127
            int kk  = (idx4 & 7) << 2;     // 0,4,...,28
            float4 v = make_float4(0.f, 0.f, 0.f, 0.f);
            int gr = r0 + row;
            if (gr < M) {
                v = *(const float4*)(A + (size_t)gr * K + k0 + kk);
                if (AMODE == 2) {
                    int kc = k0 + kk;
                    v.x = fmaxf(fmaf(v.x, g_scale[kc + 0], g_shift[kc + 0]), 0.f);
                    v.y = fmaxf(fmaf(v.y, g_scale[kc + 1], g_shift[kc + 1]), 0.f);
                    v.z = fmaxf(fmaf(v.z, g_scale[kc + 2], g_shift[kc + 2]), 0.f);
                    v.w = fmaxf(fmaf(v.w, g_scale[kc + 3], g_shift[kc + 3]), 0.f);
                }
            }
            As[kk + 0][row] = v.x;
            As[kk + 1][row] = v.y;
            As[kk + 2][row] = v.z;
            As[kk + 3][row] = v.w;
        }
        // B tile (32 k x BN)
#pragma unroll
        for (int t = tid; t < 8 * BN; t += 256) {
            int row = t / (BN / 4);
            int cc  = (t % (BN / 4)) << 2;
            *(float4*)&Bs[row][cc] =
                *(const float4*)(B + (size_t)(k0 + row) * NC + n0 + cc);
        }
        __syncthreads();
#pragma unroll
        for (int kk = 0; kk < 32; kk++) {
            // 8 A rows as 4 packed f32x2 (row pairs)
            double2 aL = *(const double2*)&As[kk][ty * 8];
            double2 aH = *(const double2*)&As[kk][ty * 8 + 4];
            double a2[4] = {aL.x, aL.y, aH.x, aH.y};
            double bd[TN];
            if (TN == 4) {
                float4 b = *(const float4*)&Bs[kk][tx * 4];
                bd[0] = dup2(b.x); bd[1] = dup2(b.y);
                bd[2] = dup2(b.z); bd[3] = dup2(b.w);
            } else {
                float2 b = *(const float2*)&Bs[kk][tx * 2];
                bd[0] = dup2(b.x); bd[1] = dup2(b.y);
            }
#pragma unroll
            for (int ip = 0; ip < 4; ip++)
#pragma unroll
                for (int j = 0; j < TN; j++)
                    acc2[ip][j] = ffma2(a2[ip], bd[j], acc2[ip][j]);
        }
        __syncthreads();
    }

    float bb[TN];
#pragma unroll
    for (int j = 0; j < TN; j++) bb[j] = bias[n0 + tx * TN + j];

    float s[TN], q[TN];
#pragma unroll
    for (int j = 0; j < TN; j++) { s[j] = 0.f; q[j] = 0.f; }

#pragma unroll
    for (int r = 0; r < 8; r++) {
        int gr = r0 + ty * 8 + r;
        if (gr < M) {
            int ip = r >> 1;
            float v[TN];
#pragma unroll
            for (int j = 0; j < TN; j++) {
                float2 u = unpack2(acc2[ip][j]);
                float c = ((r & 1) ? u.y : u.x) + bb[j];
                v[j] = c;
                if (STATS) { s[j] += c; q[j] = fmaf(c, c, q[j]); }
            }
            float* cp = C + (size_t)gr * NC + n0 + tx * TN;
            if (TN == 4) *(float4*)cp = make_float4(v[0], v[1], v[2], v[3]);
            else         *(float2*)cp = make_float2(v[0], v[1]);
        }
    }

    if (STATS) {
        // reduce across the two ty values sharing a warp (lane bit 4)
#pragma unroll
        for (int j = 0; j < TN; j++) {
            s[j] += __shfl_xor_sync(0xFFFFFFFFu, s[j], 16);
            q[j] += __shfl_xor_sync(0xFFFFFFFFu, q[j], 16);
        }
        int w = tid >> 5;
        int lane = tid & 31;
        if (lane < 16) {
#pragma unroll
            for (int j = 0; j < TN; j++) {
                ssum[w][lane * TN + j] = s[j];
                ssq[w][lane * TN + j] = q[j];
            }
        }
        __syncthreads();
        if (tid < BN) {
            float a = 0.f, b2 = 0.f;
#pragma unroll
            for (int w2 = 0; w2 < 8; w2++) { a += ssum[w2][tid]; b2 += ssq[w2][tid]; }
            atomicAdd(&g_sum[n0 + tid], a);
            atomicAdd(&g_sumsq[n0 + tid], b2);
        }
    }
}

// ---------------- BN finalize (also resets stat accumulators) ----------------
__global__ void finalize_kernel(const float* __restrict__ gamma,
                                const float* __restrict__ beta,
                                int NC, float invM) {
    int c = threadIdx.x;
    if (c < NC) {
        float mean = g_sum[c] * invM;
        float var = g_sumsq[c] * invM - mean * mean;
        float sc = gamma[c] * rsqrtf(var + BN_EPS);
        g_scale[c] = sc;
        g_shift[c] = fmaf(-mean, sc, beta[c]);
    }
    if (c < DHD) { g_sum[c] = 0.f; g_sumsq[c] = 0.f; }
}

// ---------------- fused elementwise stages ----------------
__global__ void post1_kernel(const float* __restrict__ vn) {
    int node = blockIdx.x * blockDim.y + threadIdx.y;
    if (node >= NN) return;
    int f = threadIdx.x;
    size_t idx = (size_t)node * HD + f;
    g_post[idx] = fmaxf(fmaf(g_h[idx], g_scale[f], g_shift[f]), 0.f) + vn[f];
}

__global__ void post2_kernel(const int* __restrict__ batch) {
    int node = blockIdx.x * blockDim.y + threadIdx.y;
    if (node >= NN) return;
    int f = threadIdx.x;
    size_t idx = (size_t)node * HD + f;
    float p = fmaxf(fmaf(g_h[idx], g_scale[f], g_shift[f]), 0.f);
    g_post[idx] = p;
    atomicAdd(&g_pooled[batch[node] * HD + f], p);
}

__global__ void vin_kernel(const float* __restrict__ vn) {
    int i = blockIdx.x * blockDim.x + threadIdx.x;
    if (i < NG * HD) g_vin[i] = g_pooled[i] + vn[i % HD];
}

__global__ void post3_kernel(const int* __restrict__ batch) {
    int node = blockIdx.x * blockDim.y + threadIdx.y;
    if (node >= NN) return;
    int f = threadIdx.x;
    size_t idx = (size_t)node * HD + f;
    float v = g_t2[batch[node] * HD + f];
    g_post[idx] += fmaxf(fmaf(v, g_scale[f], g_shift[f]), 0.f);
}

__global__ void readout_kernel(const int* __restrict__ batch, float* __restrict__ out) {
    int node = blockIdx.x * blockDim.y + threadIdx.y;
    if (node >= NN) return;
    int f = threadIdx.x;
    size_t idx = (size_t)node * HD + f;
    float v = fmaf(g_h[idx], g_scale[f], g_shift[f]);
    atomicAdd(&out[batch[node] * HD + f], v);
}

__global__ void div_kernel(float* __restrict__ out) {
    int i = blockIdx.x * blockDim.x + threadIdx.x;
    if (i < NG * HD) out[i] /= fmaxf(g_counts[i / HD], 1.0f);
}

// ---------------- launch ----------------
extern "C" void kernel_launch(void* const* d_in, const int* in_sizes, int n_in,
                              void* d_out, int out_size) {
    const float* x      = (const float*)d_in[0];
    const int*   edge   = (const int*)d_in[1];
    const int*   batch  = (const int*)d_in[2];
    const float* vn     = (const float*)d_in[4];
    const float* c1_W1  = (const float*)d_in[5];
    const float* c1_b1  = (const float*)d_in[6];
    const float* c1_g1  = (const float*)d_in[7];
    const float* c1_be1 = (const float*)d_in[8];
    const float* c1_W2  = (const float*)d_in[9];
    const float* c1_b2  = (const float*)d_in[10];
    const float* bn1_g  = (const float*)d_in[11];
    const float* bn1_b  = (const float*)d_in[12];
    const float* cs_W1  = (const float*)d_in[13];
    const float* cs_b1  = (const float*)d_in[14];
    const float* cs_g1  = (const float*)d_in[15];
    const float* cs_be1 = (const float*)d_in[16];
    const float* cs_W2  = (const float*)d_in[17];
    const float* cs_b2  = (const float*)d_in[18];
    const float* bns_g  = (const float*)d_in[19];
    const float* bns_b  = (const float*)d_in[20];
    const float* vm_W1  = (const float*)d_in[21];
    const float* vm_b1  = (const float*)d_in[22];
    const float* vm_g1  = (const float*)d_in[23];
    const float* vm_be1 = (const float*)d_in[24];
    const float* vm_W2  = (const float*)d_in[25];
    const float* vm_b2  = (const float*)d_in[26];
    const float* vm_g2  = (const float*)d_in[27];
    const float* vm_be2 = (const float*)d_in[28];
    float* out = (float*)d_out;

    const int* src = edge;
    const int* dst = edge + NE;

    float *p_agg, *p_z, *p_h, *p_post, *p_pooled, *p_vin, *p_t1, *p_t2, *p_counts;
    int *p_deg;
    cudaGetSymbolAddress((void**)&p_agg, g_agg);
    cudaGetSymbolAddress((void**)&p_z, g_z);
    cudaGetSymbolAddress((void**)&p_h, g_h);
    cudaGetSymbolAddress((void**)&p_post, g_post);
    cudaGetSymbolAddress((void**)&p_pooled, g_pooled);
    cudaGetSymbolAddress((void**)&p_vin, g_vin);
    cudaGetSymbolAddress((void**)&p_t1, g_t1);
    cudaGetSymbolAddress((void**)&p_t2, g_t2);
    cudaGetSymbolAddress((void**)&p_counts, g_counts);
    cudaGetSymbolAddress((void**)&p_deg, g_deg);

    dim3 ew(96, 4);
    int ewg = (NN + 3) / 4;
    const float invN = 1.0f / (float)NN;
    const float invG = 1.0f / (float)NG;
    int aggGrid = (NN + 3) / 4;

    auto g64 = [](int M) { return dim3((M + 127) / 128, DHD / 64); };  // TN=4 (NC=192)
    auto g32 = [](int M) { return dim3((M + 127) / 128, HD / 32); };   // TN=2 (NC=96)

    // ---- one-time per launch: graph counts, CSR build, stat init ----
    zero_kernel<<<1, 512>>>(p_counts, NG);
    counts_kernel<<<(NN + 255) / 256, 256>>>(batch);
    zero_stats_kernel<<<1, DHD>>>();

    zero_int_kernel<<<(NN + 1023) / 1024, 1024>>>(p_deg, NN);
    hist_kernel<<<(NE + 255) / 256, 256>>>(dst);
    scan1_kernel<<<SCAN_BLOCKS, 1024>>>();
    scan2_kernel<<<1, 32>>>();
    scan3_kernel<<<SCAN_BLOCKS, 1024>>>();
    scatter_kernel<<<(NE + 255) / 256, 256>>>(src, dst);

    // ---- layer 1 (conv1 on x) ----
    agg_csr_kernel<<<aggGrid, ew>>>(x);
    gemm2_kernel<0, 1, 4><<<g64(NN), 256>>>(p_agg, c1_W1, c1_b1, p_z, NN, HD, DHD);
    finalize_kernel<<<1, DHD>>>(c1_g1, c1_be1, DHD, invN);
    gemm2_kernel<2, 1, 2><<<g32(NN), 256>>>(p_z, c1_W2, c1_b2, p_h, NN, DHD, HD);
    finalize_kernel<<<1, DHD>>>(bn1_g, bn1_b, HD, invN);
    post1_kernel<<<ewg, ew>>>(vn);

    // ---- layer 2 (cs[0]) ----
    agg_csr_kernel<<<aggGrid, ew>>>(p_post);
    gemm2_kernel<0, 1, 4><<<g64(NN), 256>>>(p_agg, cs_W1, cs_b1, p_z, NN, HD, DHD);
    finalize_kernel<<<1, DHD>>>(cs_g1, cs_be1, DHD, invN);
    gemm2_kernel<2, 1, 2><<<g32(NN), 256>>>(p_z, cs_W2, cs_b2, p_h, NN, DHD, HD);
    finalize_kernel<<<1, DHD>>>(bns_g, bns_b, HD, invN);
    zero_kernel<<<64, 256>>>(p_pooled, NG * HD);
    post2_kernel<<<ewg, ew>>>(batch);

    // ---- virtual node MLP ----
    vin_kernel<<<(NG * HD + 255) / 256, 256>>>(vn);
    gemm2_kernel<0, 1, 4><<<g64(NG), 256>>>(p_vin, vm_W1, vm_b1, p_t1, NG, HD, DHD);
    finalize_kernel<<<1, DHD>>>(vm_g1, vm_be1, DHD, invG);
    gemm2_kernel<2, 1, 2><<<g32(NG), 256>>>(p_t1, vm_W2, vm_b2, p_t2, NG, DHD, HD);
    finalize_kernel<<<1, DHD>>>(vm_g2, vm_be2, HD, invG);
    post3_kernel<<<ewg, ew>>>(batch);

    // ---- layer 3 (cs[1]) ----
    agg_csr_kernel<<<aggGrid, ew>>>(p_post);
    gemm2_kernel<0, 1, 4><<<g64(NN), 256>>>(p_agg, cs_W1 + HD * DHD, cs_b1 + DHD,
                                            p_z, NN, HD, DHD);
    finalize_kernel<<<1, DHD>>>(cs_g1 + DHD, cs_be1 + DHD, DHD, invN);
    gemm2_kernel<2, 1, 2><<<g32(NN), 256>>>(p_z, cs_W2 + DHD * HD, cs_b2 + HD,
                                            p_h, NN, DHD, HD);
    finalize_kernel<<<1, DHD>>>(bns_g + HD, bns_b + HD, HD, invN);

    // ---- mean-pool readout ----
    zero_kernel<<<64, 256>>>(out, NG * HD);
    readout_kernel<<<ewg, ew>>>(batch, out);
    div_kernel<<<(NG * HD + 255) / 256, 256>>>(out);
}